// round 12
// baseline (speedup 1.0000x reference)
#include <cuda_runtime.h>
#include <cstdint>

#define B_SZ   8192
#define EPER   64
#define PPER   16
#define D_SZ   128
#define MN     64
#define MD     128
#define OUTD   256
#define TM     16
#define NTHR   256
#define AST    260   // padded activation row stride (floats): banks (4r+k)%32 distinct

// dynamic smem layout (bytes):
//   [0     .. 4096 )  s_eidx [TM*EPER] int
//   [4096  .. 5120 )  s_pidx [TM*PPER] int
//   [5120  .. 9216 )  s_mc   [TM*MN]   float
//   [9216  .. 17408)  s_h1   [TM*MD]   float            (stride 128)
//   [17408 .. 34048)  s_sem  [TM*AST]  float (tf32)     (stride 260)
//   [34048 .. 50688)  s_m2   [TM*AST]  float (tf32)     (stride 260)
#define SMEM_BYTES 50688

__device__ __forceinline__ float to_tf32(float x) {
    uint32_t u;
    asm("cvt.rna.tf32.f32 %0, %1;" : "=r"(u) : "f"(x));
    return __uint_as_float(u);
}

__global__ __launch_bounds__(NTHR, 4)
void subgraph_fused_kernel(const int*   __restrict__ eidx,
                           const int*   __restrict__ pidx,
                           const float* __restrict__ mc,
                           const float* __restrict__ etab,
                           const float* __restrict__ ptab,
                           const float* __restrict__ W1,
                           const float* __restrict__ b1,
                           const float* __restrict__ W2,
                           const float* __restrict__ b2,
                           const float* __restrict__ Wf,
                           const float* __restrict__ bf,
                           float*       __restrict__ out)
{
    extern __shared__ char smem_raw[];
    int*   s_eidx = (int*)smem_raw;                 // 4096 B
    int*   s_pidx = (int*)(smem_raw + 4096);        // 1024 B
    float* s_mc   = (float*)(smem_raw + 5120);      // 4096 B
    float* s_h1   = (float*)(smem_raw + 9216);      // 8192 B
    float* s_sem  = (float*)(smem_raw + 17408);     // 16640 B (tf32, stride AST)
    float* s_m2   = (float*)(smem_raw + 34048);     // 16640 B (tf32, stride AST)

    const int tid     = threadIdx.x;
    const int rowBase = blockIdx.x * TM;

    // ---- stage 0: cooperative vectorized staging ----
    {
        const int4* ge = (const int4*)(eidx + rowBase * EPER);
        if (tid < TM * EPER / 4) ((int4*)s_eidx)[tid] = ge[tid];
        const int4* gp = (const int4*)(pidx + rowBase * PPER);
        if (tid < TM * PPER / 4) ((int4*)s_pidx)[tid] = gp[tid];
        const float4* gm = (const float4*)(mc + rowBase * MN);
        if (tid < TM * MN / 4) ((float4*)s_mc)[tid] = gm[tid];
    }
    __syncthreads();

    // ---- stage 1: gather + mean pool; writes tf32-rounded s_sem ----
    {
        const int warp  = tid >> 5;
        const int wlane = tid & 31;
        const int r0    = warp * 2;
        const float4* etab4 = (const float4*)etab;
        const float4* ptab4 = (const float4*)ptab;
        const int4* idx0 = (const int4*)(s_eidx + (r0 + 0) * EPER);
        const int4* idx1 = (const int4*)(s_eidx + (r0 + 1) * EPER);
        const float se = 0.5f / EPER, sp = 0.5f / PPER;

        float4 acc0 = make_float4(0.f, 0.f, 0.f, 0.f);
        float4 acc1 = make_float4(0.f, 0.f, 0.f, 0.f);

        #pragma unroll 4
        for (int e4 = 0; e4 < EPER / 4; e4++) {
            const int4 i0 = idx0[e4];
            const int4 i1 = idx1[e4];
            const float4 v0a = etab4[(size_t)i0.x * 32 + wlane];
            const float4 v0b = etab4[(size_t)i0.y * 32 + wlane];
            const float4 v0c = etab4[(size_t)i0.z * 32 + wlane];
            const float4 v0d = etab4[(size_t)i0.w * 32 + wlane];
            const float4 v1a = etab4[(size_t)i1.x * 32 + wlane];
            const float4 v1b = etab4[(size_t)i1.y * 32 + wlane];
            const float4 v1c = etab4[(size_t)i1.z * 32 + wlane];
            const float4 v1d = etab4[(size_t)i1.w * 32 + wlane];
            acc0.x += (v0a.x + v0b.x) + (v0c.x + v0d.x);
            acc0.y += (v0a.y + v0b.y) + (v0c.y + v0d.y);
            acc0.z += (v0a.z + v0b.z) + (v0c.z + v0d.z);
            acc0.w += (v0a.w + v0b.w) + (v0c.w + v0d.w);
            acc1.x += (v1a.x + v1b.x) + (v1c.x + v1d.x);
            acc1.y += (v1a.y + v1b.y) + (v1c.y + v1d.y);
            acc1.z += (v1a.z + v1b.z) + (v1c.z + v1d.z);
            acc1.w += (v1a.w + v1b.w) + (v1c.w + v1d.w);
        }
        acc0.x *= se; acc0.y *= se; acc0.z *= se; acc0.w *= se;
        acc1.x *= se; acc1.y *= se; acc1.z *= se; acc1.w *= se;

        const int4* pdx0 = (const int4*)(s_pidx + (r0 + 0) * PPER);
        const int4* pdx1 = (const int4*)(s_pidx + (r0 + 1) * PPER);
        #pragma unroll
        for (int e4 = 0; e4 < PPER / 4; e4++) {
            const int4 i0 = pdx0[e4];
            const int4 i1 = pdx1[e4];
            const float4 v0a = ptab4[(size_t)i0.x * 32 + wlane];
            const float4 v0b = ptab4[(size_t)i0.y * 32 + wlane];
            const float4 v0c = ptab4[(size_t)i0.z * 32 + wlane];
            const float4 v0d = ptab4[(size_t)i0.w * 32 + wlane];
            const float4 v1a = ptab4[(size_t)i1.x * 32 + wlane];
            const float4 v1b = ptab4[(size_t)i1.y * 32 + wlane];
            const float4 v1c = ptab4[(size_t)i1.z * 32 + wlane];
            const float4 v1d = ptab4[(size_t)i1.w * 32 + wlane];
            acc0.x = fmaf((v0a.x + v0b.x) + (v0c.x + v0d.x), sp, acc0.x);
            acc0.y = fmaf((v0a.y + v0b.y) + (v0c.y + v0d.y), sp, acc0.y);
            acc0.z = fmaf((v0a.z + v0b.z) + (v0c.z + v0d.z), sp, acc0.z);
            acc0.w = fmaf((v0a.w + v0b.w) + (v0c.w + v0d.w), sp, acc0.w);
            acc1.x = fmaf((v1a.x + v1b.x) + (v1c.x + v1d.x), sp, acc1.x);
            acc1.y = fmaf((v1a.y + v1b.y) + (v1c.y + v1d.y), sp, acc1.y);
            acc1.z = fmaf((v1a.z + v1b.z) + (v1c.z + v1d.z), sp, acc1.z);
            acc1.w = fmaf((v1a.w + v1b.w) + (v1c.w + v1d.w), sp, acc1.w);
        }
        float4 t0, t1;
        t0.x = to_tf32(acc0.x); t0.y = to_tf32(acc0.y);
        t0.z = to_tf32(acc0.z); t0.w = to_tf32(acc0.w);
        t1.x = to_tf32(acc1.x); t1.y = to_tf32(acc1.y);
        t1.z = to_tf32(acc1.z); t1.w = to_tf32(acc1.w);
        ((float4*)(s_sem + (r0 + 0) * AST))[wlane] = t0;
        ((float4*)(s_sem + (r0 + 1) * AST))[wlane] = t1;
    }
    // no barrier: s_sem first read in stage 4 (two barriers later)

    const int lane = tid & (D_SZ - 1);
    const int grp  = tid >> 7;

    // ---- stage 2: h1 = relu(mc @ W1 + b1), fp32 ----
    {
        float a[8];
        const float bb = b1[lane];
        #pragma unroll
        for (int r = 0; r < 8; r++) a[r] = bb;
        const float4* smc4 = (const float4*)s_mc;
        #pragma unroll 4
        for (int i4 = 0; i4 < MN / 4; i4++) {
            const float w0 = W1[(4 * i4 + 0) * MD + lane];
            const float w1 = W1[(4 * i4 + 1) * MD + lane];
            const float w2 = W1[(4 * i4 + 2) * MD + lane];
            const float w3 = W1[(4 * i4 + 3) * MD + lane];
            #pragma unroll
            for (int r = 0; r < 8; r++) {
                const float4 m = smc4[(grp + 2 * r) * (MN / 4) + i4];
                float t = fmaf(m.x, w0, a[r]);
                t = fmaf(m.y, w1, t);
                t = fmaf(m.z, w2, t);
                a[r] = fmaf(m.w, w3, t);
            }
        }
        #pragma unroll
        for (int r = 0; r < 8; r++)
            s_h1[(grp + 2 * r) * MD + lane] = fmaxf(a[r], 0.f);
    }
    __syncthreads();

    // ---- stage 3: m2 = relu(h1 @ W2 + b2), fp32; tf32-rounded padded s_m2 ----
    {
        float a[8];
        const float bb = b2[lane];
        #pragma unroll
        for (int r = 0; r < 8; r++) a[r] = bb;
        const float4* sh14 = (const float4*)s_h1;
        #pragma unroll 4
        for (int i4 = 0; i4 < MD / 4; i4++) {
            const float w0 = W2[(4 * i4 + 0) * MD + lane];
            const float w1 = W2[(4 * i4 + 1) * MD + lane];
            const float w2 = W2[(4 * i4 + 2) * MD + lane];
            const float w3 = W2[(4 * i4 + 3) * MD + lane];
            #pragma unroll
            for (int r = 0; r < 8; r++) {
                const float4 h = sh14[(grp + 2 * r) * (MD / 4) + i4];
                float t = fmaf(h.x, w0, a[r]);
                t = fmaf(h.y, w1, t);
                t = fmaf(h.z, w2, t);
                a[r] = fmaf(h.w, w3, t);
            }
        }
        #pragma unroll
        for (int r = 0; r < 8; r++)
            s_m2[(grp + 2 * r) * AST + lane] = to_tf32(fmaxf(a[r], 0.f));
    }
    __syncthreads();

    // ---- stage 4: tf32 mma.sync with explicit register double-buffer prefetch ----
    // warp w owns cols [32w, 32w+32). kt = 0..31 (k8 steps over K=256).
    // Prefetch kt+1's 8 B words (raw bits via __ldg) + 4 A words BEFORE kt's MMAs.
    {
        const int warp = tid >> 5;
        const int wl   = tid & 31;
        const int fr   = wl >> 2;
        const int fk   = wl & 3;
        const int colb = warp * 32;

        // B address base: row (kt*8 + fk [+4]), col (colb + nt*8 + fr)
        const float* WfB = Wf + (size_t)fk * OUTD + colb + fr;

        float c[4][4];
        #pragma unroll
        for (int nt = 0; nt < 4; nt++)
            #pragma unroll
            for (int i = 0; i < 4; i++) c[nt][i] = 0.f;

        uint32_t bc[8], bn[8];
        uint32_t ac[4], an[4];

        #define LOAD_B(dst, kt) do {                                           \
            const float* _p = WfB + (size_t)(kt) * 8 * OUTD;                   \
            _Pragma("unroll")                                                  \
            for (int _nt = 0; _nt < 4; _nt++) {                                \
                (dst)[2*_nt+0] = __float_as_uint(__ldg(_p + _nt * 8));         \
                (dst)[2*_nt+1] = __float_as_uint(__ldg(_p + _nt * 8 + 4 * OUTD)); \
            }                                                                  \
        } while (0)

        #define LOAD_A(dst, kt) do {                                           \
            const float* _act = ((kt) < 16) ? s_sem : s_m2;                    \
            const int _kb = ((kt) & 15) * 8;                                   \
            (dst)[0] = __float_as_uint(_act[fr * AST + _kb + fk]);             \
            (dst)[1] = __float_as_uint(_act[(fr + 8) * AST + _kb + fk]);       \
            (dst)[2] = __float_as_uint(_act[fr * AST + _kb + fk + 4]);         \
            (dst)[3] = __float_as_uint(_act[(fr + 8) * AST + _kb + fk + 4]);   \
        } while (0)

        LOAD_A(ac, 0);
        LOAD_B(bc, 0);

        #pragma unroll
        for (int kt = 0; kt < 32; kt++) {
            if (kt < 31) {
                LOAD_A(an, kt + 1);
                LOAD_B(bn, kt + 1);
            }
            // cvt the already-resident B bits to tf32 (off the memory path)
            uint32_t bt[8];
            #pragma unroll
            for (int j = 0; j < 8; j++)
                asm("cvt.rna.tf32.f32 %0, %1;" : "=r"(bt[j]) : "f"(__uint_as_float(bc[j])));

            #pragma unroll
            for (int nt = 0; nt < 4; nt++) {
                asm volatile(
                    "mma.sync.aligned.m16n8k8.row.col.f32.tf32.tf32.f32 "
                    "{%0,%1,%2,%3}, {%4,%5,%6,%7}, {%8,%9}, {%0,%1,%2,%3};"
                    : "+f"(c[nt][0]), "+f"(c[nt][1]), "+f"(c[nt][2]), "+f"(c[nt][3])
                    : "r"(ac[0]), "r"(ac[1]), "r"(ac[2]), "r"(ac[3]),
                      "r"(bt[2*nt]), "r"(bt[2*nt+1]));
            }

            #pragma unroll
            for (int j = 0; j < 8; j++) bc[j] = bn[j];
            #pragma unroll
            for (int j = 0; j < 4; j++) ac[j] = an[j];
        }
        #undef LOAD_B
        #undef LOAD_A

        // epilogue: c0=(fr,2fk), c1=(fr,2fk+1), c2=(fr+8,2fk), c3=(fr+8,2fk+1)
        #pragma unroll
        for (int nt = 0; nt < 4; nt++) {
            const int cb = colb + nt * 8 + 2 * fk;
            const float2 bfv = *(const float2*)(bf + cb);
            float2 o0, o1;
            o0.x = fmaxf(c[nt][0] + bfv.x, 0.f);
            o0.y = fmaxf(c[nt][1] + bfv.y, 0.f);
            o1.x = fmaxf(c[nt][2] + bfv.x, 0.f);
            o1.y = fmaxf(c[nt][3] + bfv.y, 0.f);
            *(float2*)(out + (size_t)(rowBase + fr) * OUTD + cb)     = o0;
            *(float2*)(out + (size_t)(rowBase + fr + 8) * OUTD + cb) = o1;
        }
    }
}

extern "C" void kernel_launch(void* const* d_in, const int* in_sizes, int n_in,
                              void* d_out, int out_size)
{
    const int*   eidx = (const int*)d_in[0];
    const int*   pidx = (const int*)d_in[1];
    const float* mc   = (const float*)d_in[2];
    const float* etab = (const float*)d_in[3];
    const float* ptab = (const float*)d_in[4];
    const float* W1   = (const float*)d_in[5];
    const float* b1   = (const float*)d_in[6];
    const float* W2   = (const float*)d_in[7];
    const float* b2   = (const float*)d_in[8];
    const float* Wf   = (const float*)d_in[9];
    const float* bf   = (const float*)d_in[10];
    float* out = (float*)d_out;

    cudaFuncSetAttribute(subgraph_fused_kernel,
                         cudaFuncAttributeMaxDynamicSharedMemorySize, SMEM_BYTES);

    subgraph_fused_kernel<<<B_SZ / TM, NTHR, SMEM_BYTES>>>(
        eidx, pidx, mc, etab, ptab, W1, b1, W2, b2, Wf, bf, out);
}